// round 16
// baseline (speedup 1.0000x reference)
#include <cuda_runtime.h>

#define SEQ   4096
#define BATCH 4096
#define NIN   2
#define HID   8
#define CTAS  128
#define BPC   (BATCH / CTAS)   // 32 batches per CTA
#define GRP   16               // groups per chain-slot; thread owns g and g+GRP
#define TPB   (GRP * HID)      // 128 threads, each carrying TWO recurrences

typedef unsigned long long u64;

// MUFU.TANH: single-instruction tanh (sm_75+), max abs err ~2^-10.7
__device__ __forceinline__ float tanhap_(float x) {
    float y; asm("tanh.approx.f32 %0, %1;" : "=f"(y) : "f"(x)); return y;
}

// Pack two floats into a b64 register pair.
__device__ __forceinline__ u64 pk2(float lo, float hi) {
    u64 d;
    asm("mov.b64 %0, {%1, %2};" : "=l"(d)
        : "r"(__float_as_uint(lo)), "r"(__float_as_uint(hi)));
    return d;
}
__device__ __forceinline__ void upk2(u64 v, float& lo, float& hi) {
    unsigned a, b;
    asm("mov.b64 {%0, %1}, %2;" : "=r"(a), "=r"(b) : "l"(v));
    lo = __uint_as_float(a); hi = __uint_as_float(b);
}

// Packed fp32x2 ops on b64 carriers — single SASS instruction each.
__device__ __forceinline__ u64 ffma2(u64 a, u64 b, u64 c) {
    u64 d; asm("fma.rn.f32x2 %0, %1, %2, %3;" : "=l"(d) : "l"(a), "l"(b), "l"(c)); return d;
}
__device__ __forceinline__ u64 fmul2(u64 a, u64 b) {
    u64 d; asm("mul.rn.f32x2 %0, %1, %2;" : "=l"(d) : "l"(a), "l"(b)); return d;
}
__device__ __forceinline__ u64 fadd2(u64 a, u64 b) {
    u64 d; asm("add.rn.f32x2 %0, %1, %2;" : "=l"(d) : "l"(a), "l"(b)); return d;
}

// Compiler-only memory fence (no WARPSYNC). Same-warp LSU ordering covers the
// single-buffer STS->LDS handoff (proven R9/R11).
__device__ __forceinline__ void memfence_compiler() {
    asm volatile("" ::: "memory");
}

__global__ void __launch_bounds__(TPB) lstm_kernel(
    const float* __restrict__ x,
    const float* __restrict__ h0,
    const float* __restrict__ c0,
    const float* __restrict__ W_ih,
    const float* __restrict__ W_hh,
    const float* __restrict__ b_ih,
    const float* __restrict__ b_hh,
    float* __restrict__ out)
{
    const int tid = threadIdx.x;
    const int g   = tid >> 3;   // group 0..15 (chain A); chain B = g + 16
    const int j   = tid & 7;    // h index within batch
    const int bA  = blockIdx.x * BPC + g;
    const int bB  = bA + GRP;

    // Gate rows owned by this lane (PyTorch order i,f,g,o)
    const int ri = j, rf = 8 + j, rg = 16 + j, ro = 24 + j;
    // sigmoid(u) = 0.5*tanh(u/2)+0.5 -> fold the 1/2 into rows i,f,o.
    const float si = 0.5f, sf = 0.5f, sg = 1.0f, so = 0.5f;

    // Pair-packed weights — indexed by j only, SHARED by both chains.
    u64 wig_h[HID], wfo_h[HID];
    #pragma unroll
    for (int k = 0; k < HID; k++) {
        wig_h[k] = pk2(si * W_hh[ri * HID + k], sg * W_hh[rg * HID + k]);
        wfo_h[k] = pk2(sf * W_hh[rf * HID + k], so * W_hh[ro * HID + k]);
    }
    const u64 wig_x0 = pk2(si * W_ih[ri * NIN + 0], sg * W_ih[rg * NIN + 0]);
    const u64 wig_x1 = pk2(si * W_ih[ri * NIN + 1], sg * W_ih[rg * NIN + 1]);
    const u64 wfo_x0 = pk2(sf * W_ih[rf * NIN + 0], so * W_ih[ro * NIN + 0]);
    const u64 wfo_x1 = pk2(sf * W_ih[rf * NIN + 1], so * W_ih[ro * NIN + 1]);
    const u64 big = pk2(si * (b_ih[ri] + b_hh[ri]), sg * (b_ih[rg] + b_hh[rg]));
    const u64 bfo = pk2(sf * (b_ih[rf] + b_hh[rf]), so * (b_ih[ro] + b_hh[ro]));

    // h exchange: duplicated (h,h) pairs, single buffer, pipelined handoff.
    __shared__ __align__(16) u64 sh[BPC][HID];

    float cA = c0[bA * HID + j], hA = h0[bA * HID + j];
    float cB = c0[bB * HID + j], hB = h0[bB * HID + j];

    const size_t xstride = (size_t)BATCH * NIN;
    const float* xbaseA = x + (size_t)bA * NIN;
    const float* xbaseB = x + (size_t)bB * NIN;
    auto ldxA = [&](int s) -> float2 {
        int sc = s < SEQ ? s : (SEQ - 1);
        return *(const float2*)(xbaseA + (size_t)sc * xstride);
    };
    auto ldxB = [&](int s) -> float2 {
        int sc = s < SEQ ? s : (SEQ - 1);
        return *(const float2*)(xbaseB + (size_t)sc * xstride);
    };

    // Prologue: publish h(0) for both chains, preload pipeline registers.
    sh[g      ][j] = pk2(hA, hA);
    sh[g + GRP][j] = pk2(hB, hB);
    __syncwarp();
    ulonglong2 PA0, PA1, PA2, PA3, PB0, PB1, PB2, PB3;
    {
        const ulonglong2* hpA = (const ulonglong2*)&sh[g][0];
        PA0 = hpA[0]; PA1 = hpA[1]; PA2 = hpA[2]; PA3 = hpA[3];
        const ulonglong2* hpB = (const ulonglong2*)&sh[g + GRP][0];
        PB0 = hpB[0]; PB1 = hpB[1]; PB2 = hpB[2]; PB3 = hpB[3];
    }

    // 4-deep x prefetch per chain (superstep cadence ~2x slower per chain).
    float2 xqA0 = ldxA(1), xqA1 = ldxA(2), xqA2 = ldxA(3), xqA3 = ldxA(4);
    float2 xqB0 = ldxB(1), xqB1 = ldxB(2), xqB2 = ldxB(3), xqB3 = ldxB(4);
    u64 xpigA, xpfoA, xpigB, xpfoB;
    {
        float2 x0 = ldxA(0);
        u64 x0d = pk2(x0.x, x0.x), x1d = pk2(x0.y, x0.y);
        xpigA = ffma2(wig_x1, x1d, ffma2(wig_x0, x0d, big));
        xpfoA = ffma2(wfo_x1, x1d, ffma2(wfo_x0, x0d, bfo));
        float2 y0 = ldxB(0);
        u64 y0d = pk2(y0.x, y0.x), y1d = pk2(y0.y, y0.y);
        xpigB = ffma2(wig_x1, y1d, ffma2(wig_x0, y0d, big));
        xpfoB = ffma2(wfo_x1, y1d, ffma2(wfo_x0, y0d, bfo));
    }

    // Gate accumulation tree for one chain (4-way, depth 2 FFMA2 + 2 fadd2).
    auto tree = [&](ulonglong2 p0, ulonglong2 p1, ulonglong2 p2, ulonglong2 p3,
                    u64 xpig, u64 xpfo, u64& Aig, u64& Afo) {
        u64 aA = ffma2(wig_h[0], p0.x, xpig);
        u64 gA = ffma2(wfo_h[0], p0.x, xpfo);
        u64 aB = fmul2(wig_h[1], p0.y);
        u64 gB = fmul2(wfo_h[1], p0.y);
        u64 aC = fmul2(wig_h[2], p1.x);
        u64 gC = fmul2(wfo_h[2], p1.x);
        u64 aD = fmul2(wig_h[3], p1.y);
        u64 gD = fmul2(wfo_h[3], p1.y);
        aA = ffma2(wig_h[4], p2.x, aA);  gA = ffma2(wfo_h[4], p2.x, gA);
        aB = ffma2(wig_h[5], p2.y, aB);  gB = ffma2(wfo_h[5], p2.y, gB);
        aC = ffma2(wig_h[6], p3.x, aC);  gC = ffma2(wfo_h[6], p3.x, gC);
        aD = ffma2(wig_h[7], p3.y, aD);  gD = ffma2(wfo_h[7], p3.y, gD);
        Aig = fadd2(fadd2(aA, aB), fadd2(aC, aD));
        Afo = fadd2(fadd2(gA, gB), fadd2(gC, gD));
    };

    // One superstep: advance BOTH chains one timestep, interleaved so each
    // chain's FMA work fills the other's MUFU round-trip windows.
    auto dostep2 = [&](float2 xnA, float2& farA, int sfA,
                       float2 xnB, float2& farB, int sfB) {
        ulonglong2 pA0 = PA0, pA1 = PA1, pA2 = PA2, pA3 = PA3;
        ulonglong2 pB0 = PB0, pB1 = PB1, pB2 = PB2, pB3 = PB3;
        float hcA = 0.5f * cA;
        float hcB = 0.5f * cB;

        // --- Chain A tree + gate tanh issues
        u64 AigA, AfoA;
        tree(pA0, pA1, pA2, pA3, xpigA, xpfoA, AigA, AfoA);
        float aiA, agA, afA, aoA;
        upk2(AigA, aiA, agA);
        upk2(AfoA, afA, aoA);
        float tiA = tanhap_(aiA);
        float tgA = tanhap_(agA);
        float tfA = tanhap_(afA);
        float toA = tanhap_(aoA);

        // --- Chain B tree + gate tanh issues (fills A's gate-RT window)
        u64 AigB, AfoB;
        tree(pB0, pB1, pB2, pB3, xpigB, xpfoB, AigB, AfoB);
        float aiB, agB, afB, aoB;
        upk2(AigB, aiB, agB);
        upk2(AfoB, afB, aoB);
        float tiB = tanhap_(aiB);
        float tgB = tanhap_(agB);
        float tfB = tanhap_(afB);
        float toB = tanhap_(aoB);

        // --- A's window fill: next-x projection leg for A + far prefetch
        u64 xadA = pk2(xnA.x, xnA.x), xbdA = pk2(xnA.y, xnA.y);
        u64 t1A = ffma2(wig_x0, xadA, big);
        u64 t2A = ffma2(wfo_x0, xadA, bfo);
        farA = ldxA(sfA);

        // --- Chain A cell update + tanh(c) issue
        float siA = fmaf(0.5f, tiA, 0.5f);
        float qA  = fmaf(siA, tgA, hcA);
        cA = fmaf(hcA, tfA, qA);
        float tcA = tanhap_(cA);

        // --- B's window fill: next-x projection leg for B + far prefetch
        u64 xadB = pk2(xnB.x, xnB.x), xbdB = pk2(xnB.y, xnB.y);
        u64 t1B = ffma2(wig_x0, xadB, big);
        u64 t2B = ffma2(wfo_x0, xadB, bfo);
        farB = ldxB(sfB);

        // --- Chain B cell update + tanh(c) issue (fills A's tanhc-RT)
        float siB = fmaf(0.5f, tiB, 0.5f);
        float qB  = fmaf(siB, tgB, hcB);
        cB = fmaf(hcB, tfB, qB);
        float tcB = tanhap_(cB);

        // --- finish x projections (more window fill)
        u64 nigA = ffma2(wig_x1, xbdA, t1A);
        u64 nfoA = ffma2(wfo_x1, xbdA, t2A);
        u64 nigB = ffma2(wig_x1, xbdB, t1B);
        u64 nfoB = ffma2(wfo_x1, xbdB, t2B);

        // --- Chain A h + exchange handoff
        float soA = fmaf(0.5f, toA, 0.5f);
        hA = soA * tcA;
        sh[g][j] = pk2(hA, hA);
        memfence_compiler();
        {
            const ulonglong2* hp = (const ulonglong2*)&sh[g][0];
            PA0 = hp[0]; PA1 = hp[1]; PA2 = hp[2]; PA3 = hp[3];
        }

        // --- Chain B h + exchange handoff
        float soB = fmaf(0.5f, toB, 0.5f);
        hB = soB * tcB;
        sh[g + GRP][j] = pk2(hB, hB);
        memfence_compiler();
        {
            const ulonglong2* hp = (const ulonglong2*)&sh[g + GRP][0];
            PB0 = hp[0]; PB1 = hp[1]; PB2 = hp[2]; PB3 = hp[3];
        }

        xpigA = nigA; xpfoA = nfoA;
        xpigB = nigB; xpfoB = nfoB;
    };

    #pragma unroll 1
    for (int s = 0; s < SEQ; s += 4) {
        dostep2(xqA0, xqA0, s + 5, xqB0, xqB0, s + 5);
        dostep2(xqA1, xqA1, s + 6, xqB1, xqB1, s + 6);
        dostep2(xqA2, xqA2, s + 7, xqB2, xqB2, s + 7);
        dostep2(xqA3, xqA3, s + 8, xqB3, xqB3, s + 8);
    }

    out[bA * HID + j] = hA;
    out[bB * HID + j] = hB;
}

extern "C" void kernel_launch(void* const* d_in, const int* in_sizes, int n_in,
                              void* d_out, int out_size) {
    const float* x    = (const float*)d_in[0];
    const float* h0   = (const float*)d_in[1];
    const float* c0   = (const float*)d_in[2];
    const float* W_ih = (const float*)d_in[3];
    const float* W_hh = (const float*)d_in[4];
    const float* b_ih = (const float*)d_in[5];
    const float* b_hh = (const float*)d_in[6];
    lstm_kernel<<<CTAS, TPB>>>(x, h0, c0, W_ih, W_hh, b_ih, b_hh, (float*)d_out);
}

// round 17
// speedup vs baseline: 1.2846x; 1.2846x over previous
#include <cuda_runtime.h>

#define SEQ   4096
#define BATCH 4096
#define NIN   2
#define HID   8
#define CTAS  128
#define BPC   (BATCH / CTAS)   // 32 batches per CTA
#define TPB   (BPC * HID)      // 256 threads

typedef unsigned long long u64;

// MUFU.TANH: single-instruction tanh (sm_75+), max abs err ~2^-10.7
__device__ __forceinline__ float tanhap_(float x) {
    float y; asm("tanh.approx.f32 %0, %1;" : "=f"(y) : "f"(x)); return y;
}

// Pack two floats into a b64 register pair.
__device__ __forceinline__ u64 pk2(float lo, float hi) {
    u64 d;
    asm("mov.b64 %0, {%1, %2};" : "=l"(d)
        : "r"(__float_as_uint(lo)), "r"(__float_as_uint(hi)));
    return d;
}
__device__ __forceinline__ void upk2(u64 v, float& lo, float& hi) {
    unsigned a, b;
    asm("mov.b64 {%0, %1}, %2;" : "=r"(a), "=r"(b) : "l"(v));
    lo = __uint_as_float(a); hi = __uint_as_float(b);
}

// Packed fp32x2 ops on b64 carriers — single SASS instruction each.
__device__ __forceinline__ u64 ffma2(u64 a, u64 b, u64 c) {
    u64 d; asm("fma.rn.f32x2 %0, %1, %2, %3;" : "=l"(d) : "l"(a), "l"(b), "l"(c)); return d;
}
__device__ __forceinline__ u64 fmul2(u64 a, u64 b) {
    u64 d; asm("mul.rn.f32x2 %0, %1, %2;" : "=l"(d) : "l"(a), "l"(b)); return d;
}
__device__ __forceinline__ u64 fadd2(u64 a, u64 b) {
    u64 d; asm("add.rn.f32x2 %0, %1, %2;" : "=l"(d) : "l"(a), "l"(b)); return d;
}

// Compiler-only memory fence (no WARPSYNC emitted). Same-warp LSU ordering
// guarantees the hoisted LDS sees all lanes' preceding STS (proven R9/R11).
__device__ __forceinline__ void memfence_compiler() {
    asm volatile("" ::: "memory");
}

__global__ void __launch_bounds__(TPB) lstm_kernel(
    const float* __restrict__ x,
    const float* __restrict__ h0,
    const float* __restrict__ c0,
    const float* __restrict__ W_ih,
    const float* __restrict__ W_hh,
    const float* __restrict__ b_ih,
    const float* __restrict__ b_hh,
    float* __restrict__ out)
{
    const int tid = threadIdx.x;
    const int g   = tid >> 3;   // batch group within CTA
    const int j   = tid & 7;    // h index within batch
    const int b   = blockIdx.x * BPC + g;

    // Gate rows owned by this lane (PyTorch order i,f,g,o)
    const int ri = j, rf = 8 + j, rg = 16 + j, ro = 24 + j;
    // sigmoid(u) = 0.5*tanh(u/2)+0.5 -> fold the 1/2 into rows i,f,o.
    const float si = 0.5f, sf = 0.5f, sg = 1.0f, so = 0.5f;

    // Pair-packed weights as b64 carriers: (i,g) pair and (f,o) pair.
    u64 wig_h[HID], wfo_h[HID];
    #pragma unroll
    for (int k = 0; k < HID; k++) {
        wig_h[k] = pk2(si * W_hh[ri * HID + k], sg * W_hh[rg * HID + k]);
        wfo_h[k] = pk2(sf * W_hh[rf * HID + k], so * W_hh[ro * HID + k]);
    }
    const u64 wig_x0 = pk2(si * W_ih[ri * NIN + 0], sg * W_ih[rg * NIN + 0]);
    const u64 wig_x1 = pk2(si * W_ih[ri * NIN + 1], sg * W_ih[rg * NIN + 1]);
    const u64 wfo_x0 = pk2(sf * W_ih[rf * NIN + 0], so * W_ih[ro * NIN + 0]);
    const u64 wfo_x1 = pk2(sf * W_ih[rf * NIN + 1], so * W_ih[ro * NIN + 1]);
    const u64 big = pk2(si * (b_ih[ri] + b_hh[ri]), sg * (b_ih[rg] + b_hh[rg]));
    const u64 bfo = pk2(sf * (b_ih[rf] + b_hh[rf]), so * (b_ih[ro] + b_hh[ro]));

    // h exchange: duplicated (h,h) pairs, SINGLE buffer, software-pipelined
    // one step ahead (LDS issued right after the STS; consumed next step).
    __shared__ __align__(16) u64 sh[BPC][HID];

    float c = c0[b * HID + j];
    float h = h0[b * HID + j];

    const size_t xstride = (size_t)BATCH * NIN;
    const float* xbase = x + (size_t)b * NIN;
    auto ldx = [&](int s) -> float2 {
        int sc = s < SEQ ? s : (SEQ - 1);
        return *(const float2*)(xbase + (size_t)sc * xstride);
    };

    // Prologue: publish h(0), pre-load pipeline registers.
    sh[g][j] = pk2(h, h);
    __syncwarp();
    ulonglong2 P0, P1, P2, P3;
    {
        const ulonglong2* hp = (const ulonglong2*)&sh[g][0];
        P0 = hp[0]; P1 = hp[1]; P2 = hp[2]; P3 = hp[3];
    }

    // 8-deep x prefetch for the 8x-unrolled loop.
    float2 xq0 = ldx(1), xq1 = ldx(2), xq2 = ldx(3), xq3 = ldx(4);
    float2 xq4 = ldx(5), xq5 = ldx(6), xq6 = ldx(7), xq7 = ldx(8);
    u64 xpig, xpfo;
    {
        float2 x0 = ldx(0);
        u64 x0d = pk2(x0.x, x0.x);
        u64 x1d = pk2(x0.y, x0.y);
        xpig = ffma2(wig_x1, x1d, ffma2(wig_x0, x0d, big));
        xpfo = ffma2(wfo_x1, x1d, ffma2(wfo_x0, x0d, bfo));
    }

    // One step. xnext: x[s+1] (already prefetched). pf: address of the far
    // prefetch (LDG [reg+imm] in the main loop — no per-step index math).
    auto dostep = [&](float2 xnext, float2& xfar, const float2* pf) {
        // Consume h pairs whose LDS was issued at the end of the previous step.
        ulonglong2 p0 = P0, p1 = P1, p2 = P2, p3 = P3;

        float hc = 0.5f * c;   // off-chain half*c

        // Four-way accumulation trees per gate-pair (depth 2 FFMA2 + 2 fadd2)
        u64 aA = ffma2(wig_h[0], p0.x, xpig);
        u64 gA = ffma2(wfo_h[0], p0.x, xpfo);
        u64 aB = fmul2(wig_h[1], p0.y);
        u64 gB = fmul2(wfo_h[1], p0.y);
        u64 aC = fmul2(wig_h[2], p1.x);
        u64 gC = fmul2(wfo_h[2], p1.x);
        u64 aD = fmul2(wig_h[3], p1.y);
        u64 gD = fmul2(wfo_h[3], p1.y);
        aA = ffma2(wig_h[4], p2.x, aA);  gA = ffma2(wfo_h[4], p2.x, gA);
        aB = ffma2(wig_h[5], p2.y, aB);  gB = ffma2(wfo_h[5], p2.y, gB);
        aC = ffma2(wig_h[6], p3.x, aC);  gC = ffma2(wfo_h[6], p3.x, gC);
        aD = ffma2(wig_h[7], p3.y, aD);  gD = ffma2(wfo_h[7], p3.y, gD);
        u64 aAB = fadd2(aA, aB);
        u64 gAB = fadd2(gA, gB);
        u64 aCD = fadd2(aC, aD);
        u64 gCD = fadd2(gC, gD);
        u64 Aig = fadd2(aAB, aCD);
        u64 Afo = fadd2(gAB, gCD);

        float a_i, a_g, a_f, a_o;
        upk2(Aig, a_i, a_g);
        upk2(Afo, a_f, a_o);

        // Gate tanhs, issue order i,g,f,o (c waits on f; o trails for free).
        float t_i = tanhap_(a_i);   // a_i = u_i/2
        float t_g = tanhap_(a_g);   // true tanh(g)
        float t_f = tanhap_(a_f);
        float t_o = tanhap_(a_o);

        // ---- Gate-RT window fill: next x-projection leg A + far prefetch.
        u64 x0d = pk2(xnext.x, xnext.x);
        u64 x1d = pk2(xnext.y, xnext.y);
        u64 t1 = ffma2(wig_x0, x0d, big);
        u64 t2 = ffma2(wfo_x0, x0d, bfo);
        xfar = *pf;                 // GMEM prefetch, pure latency overlap

        // c = 0.5*t_f*c + (0.5*c + s_i*t_g), s_i = 0.5*t_i + 0.5
        float s_i = fmaf(0.5f, t_i, 0.5f);
        float q   = fmaf(s_i, t_g, hc);
        c = fmaf(hc, t_f, q);

        float t_c = tanhap_(c);     // second MUFU round-trip

        // ---- tanhc-RT window fill: x-projection leg B.
        u64 nig = ffma2(wig_x1, x1d, t1);
        u64 nfo = ffma2(wfo_x1, x1d, t2);

        float s_o = fmaf(0.5f, t_o, 0.5f);
        h = s_o * t_c;

        // Publish h and IMMEDIATELY issue next step's exchange loads;
        // the LDS round-trip overlaps the handoff + loop overhead (R11).
        sh[g][j] = pk2(h, h);
        memfence_compiler();
        {
            const ulonglong2* hp = (const ulonglong2*)&sh[g][0];
            P0 = hp[0]; P1 = hp[1]; P2 = hp[2]; P3 = hp[3];
        }

        xpig = nig; xpfo = nfo;
    };

    // Main loop: unclamped far-prefetch via running pointer + imm offsets.
    // Covers s in [0, SEQ-24); max prefetch index = (SEQ-32)+16 = SEQ-16 < SEQ.
    const float* xcur = xbase + 9 * xstride;   // points at x[s+9] for s=0
    #pragma unroll 1
    for (int s = 0; s < SEQ - 24; s += 8) {
        dostep(xq0, xq0, (const float2*)(xcur + 0 * xstride));
        dostep(xq1, xq1, (const float2*)(xcur + 1 * xstride));
        dostep(xq2, xq2, (const float2*)(xcur + 2 * xstride));
        dostep(xq3, xq3, (const float2*)(xcur + 3 * xstride));
        dostep(xq4, xq4, (const float2*)(xcur + 4 * xstride));
        dostep(xq5, xq5, (const float2*)(xcur + 5 * xstride));
        dostep(xq6, xq6, (const float2*)(xcur + 6 * xstride));
        dostep(xq7, xq7, (const float2*)(xcur + 7 * xstride));
        xcur += 8 * xstride;
    }

    // Tail: 24 steps with clamped prefetch addresses (index math OK here).
    #pragma unroll 1
    for (int s = SEQ - 24; s < SEQ; s += 8) {
        float2 dummy;
        // prefetch targets s+9..s+16, clamped to SEQ-1
        auto pfp = [&](int k) -> const float2* {
            int sc = s + 9 + k; if (sc > SEQ - 1) sc = SEQ - 1;
            return (const float2*)(xbase + (size_t)sc * xstride);
        };
        dostep(xq0, xq0, pfp(0));
        dostep(xq1, xq1, pfp(1));
        dostep(xq2, xq2, pfp(2));
        dostep(xq3, xq3, pfp(3));
        dostep(xq4, xq4, pfp(4));
        dostep(xq5, xq5, pfp(5));
        dostep(xq6, xq6, pfp(6));
        dostep(xq7, xq7, pfp(7));
        (void)dummy;
    }

    out[b * HID + j] = h;
}

extern "C" void kernel_launch(void* const* d_in, const int* in_sizes, int n_in,
                              void* d_out, int out_size) {
    const float* x    = (const float*)d_in[0];
    const float* h0   = (const float*)d_in[1];
    const float* c0   = (const float*)d_in[2];
    const float* W_ih = (const float*)d_in[3];
    const float* W_hh = (const float*)d_in[4];
    const float* b_ih = (const float*)d_in[5];
    const float* b_hh = (const float*)d_in[6];
    lstm_kernel<<<CTAS, TPB>>>(x, h0, c0, W_ih, W_hh, b_ih, b_hh, (float*)d_out);
}